// round 15
// baseline (speedup 1.0000x reference)
#include <cuda_runtime.h>
#include <cuda_bf16.h>
#include <cstdint>

#define IN_F   4096
#define OUT_F  768
#define BITS   6144
#define BATCH  1024

#define BM 64
#define BN 64
#define BKK 64
#define KSPLIT 2
#define KSLICE (IN_F / KSPLIT)   // 2048
#define NKC (KSLICE / BKK)       // 32
#define NSTAGE 4
#define GX (OUT_F / BN)          // 12
#define GY (BATCH / BM)          // 16
#define NTILE (GX * GY)          // 192 gemm tiles per z-slice
#define A_ST (BM * BKK)
#define B_ST (BN * BKK)
#define DSMEM_BYTES (NSTAGE * (A_ST + B_ST) * 2)   // 65536
#define NLOSS 768
#define NWB_HALF 1536            // weight blocks per k-half

// ---------------- device scratch ----------------
__device__ __nv_bfloat16 g_wT[(size_t)OUT_F * IN_F];
__device__ __nv_bfloat16 g_lat[(size_t)BATCH * IN_F];
__device__ float g_pred[KSPLIT][(size_t)BATCH * OUT_F];
__device__ float g_reg_part[3072];
__device__ float g_recon_part[NLOSS];
__device__ int   g_ticket;

// ---------------- helpers ----------------
__device__ __forceinline__ float tanh_fast(float x) {
    float y; asm("tanh.approx.f32 %0, %1;" : "=f"(y) : "f"(x)); return y;
}
__device__ __forceinline__ uint32_t cvta_s(const void* p) {
    return (uint32_t)__cvta_generic_to_shared(p);
}
#define CP_ASYNC16(s, g) asm volatile("cp.async.cg.shared.global [%0], [%1], 16;\n" :: "r"(s), "l"(g))
#define CP_COMMIT        asm volatile("cp.async.commit_group;\n" ::: "memory")
#define CP_WAIT0         asm volatile("cp.async.wait_group 0;\n" ::: "memory")
#define CP_WAIT1         asm volatile("cp.async.wait_group 1;\n" ::: "memory")
#define CP_WAIT2         asm volatile("cp.async.wait_group 2;\n" ::: "memory")
#define LDSM4(r0, r1, r2, r3, a) \
    asm volatile("ldmatrix.sync.aligned.m8n8.x4.shared.b16 {%0,%1,%2,%3}, [%4];\n" \
                 : "=r"(r0), "=r"(r1), "=r"(r2), "=r"(r3) : "r"(a))
#define MMA(d, a, b0, b1) \
    asm volatile("mma.sync.aligned.m16n8k16.row.col.f32.bf16.bf16.f32 " \
                 "{%0,%1,%2,%3},{%4,%5,%6,%7},{%8,%9},{%0,%1,%2,%3};\n" \
                 : "+f"(d[0]), "+f"(d[1]), "+f"(d[2]), "+f"(d[3]) \
                 : "r"(a[0]), "r"(a[1]), "r"(a[2]), "r"(a[3]), "r"(b0), "r"(b1))

// ---------------- weight-transform block (32x32 tile at k0,n0) ----------------
__device__ __forceinline__ void weight_block(const float* __restrict__ w,
                                             int k0, int n0, int part_idx, int t) {
    __shared__ float s_iw[32][33];
    __shared__ float s_red[8];
    const float pwh[8] = {0.5f, 1.f, 2.f, 4.f, 8.f, 16.f, 32.f, -64.f};

    float regloc = 0.f;
#pragma unroll
    for (int i = 0; i < 4; i++) {
        int c = t + i * 256;
        int kk = c >> 5, nn = c & 31;
        const float4* p = reinterpret_cast<const float4*>(
            w + (size_t)(k0 + kk) * BITS + (size_t)(n0 + nn) * 8);
        float4 w0 = p[0], w1 = p[1];
        float xs[8] = {w0.x, w0.y, w0.z, w0.w, w1.x, w1.y, w1.z, w1.w};
        float iwt = 0.f, sab = 0.f;
#pragma unroll
        for (int b = 0; b < 8; b++) {
            float th = tanh_fast(0.5f * xs[b]);
            iwt = fmaf(th, pwh[b], iwt);
            sab += fabsf(th);
        }
        s_iw[kk][nn] = iwt - 0.5f;
        regloc += fmaf(-0.5f, sab, 4.0f);
    }
    __syncthreads();
#pragma unroll
    for (int i = 0; i < 4; i++) {
        int c = t + i * 256;
        int nn = c >> 5, kk = c & 31;
        g_wT[(size_t)(n0 + nn) * IN_F + (k0 + kk)] = __float2bfloat16(s_iw[kk][nn]);
    }
#pragma unroll
    for (int o = 16; o > 0; o >>= 1)
        regloc += __shfl_xor_sync(0xffffffffu, regloc, o);
    if ((t & 31) == 0) s_red[t >> 5] = regloc;
    __syncthreads();
    if (t == 0) {
        float s = 0.f;
#pragma unroll
        for (int i = 0; i < 8; i++) s += s_red[i];
        g_reg_part[part_idx] = s;
    }
}

// ---------------- preA: weights k<2048 + latent conversion ----------------
__global__ void k_preA(const float* __restrict__ w, const float* __restrict__ lat) {
    int bx = blockIdx.x;
    int t = threadIdx.x;
    if (bx < NWB_HALF) {
        weight_block(w, (bx & 63) * 32, (bx >> 6) * 32, bx, t);
    } else {
        int i = (bx - NWB_HALF) * 256 + t;
        const int stride = 1024 * 256;
        const float4* src = reinterpret_cast<const float4*>(lat);
        __nv_bfloat162* o = reinterpret_cast<__nv_bfloat162*>(g_lat);
        float4 v[4];
#pragma unroll
        for (int j = 0; j < 4; j++) v[j] = src[i + j * stride];
#pragma unroll
        for (int j = 0; j < 4; j++) {
            int idx = i + j * stride;
            o[2 * idx]     = __floats2bfloat162_rn(v[j].x, v[j].y);
            o[2 * idx + 1] = __floats2bfloat162_rn(v[j].z, v[j].w);
        }
    }
}

// int_sum(r,n)/255 from true_sum
__device__ __forceinline__ float tval(const float* __restrict__ ts, int r, int n) {
    const float4* p = reinterpret_cast<const float4*>(ts + ((size_t)r * OUT_F + n) * 8);
    float4 a = p[0], b = p[1];
    return (a.x + 2.f * a.y + 4.f * a.z + 8.f * a.w
            + 16.f * b.x + 32.f * b.y + 64.f * b.z - 128.f * b.w) * (1.0f / 255.0f);
}

// stage loader (R14 verbatim)
__device__ __forceinline__ void load_tile(
    uint16_t* Asb, uint16_t* Bsb,
    const __nv_bfloat16* gA, const __nv_bfloat16* gB, int kbase, int t)
{
#pragma unroll
    for (int j = 0; j < 2; j++) {
        int id = t + j * 256;
        int row = id >> 3, c = id & 7;
        int sw = (c ^ (row & 7)) << 3;
        CP_ASYNC16(cvta_s(&Asb[row * BKK + sw]),
                   gA + (size_t)row * IN_F + kbase + c * 8);
        CP_ASYNC16(cvta_s(&Bsb[row * BKK + sw]),
                   gB + (size_t)row * IN_F + kbase + c * 8);
    }
}

// ---------------- GEMM tile body (R14 verbatim, parametrized) ----------------
__device__ __forceinline__ void gemm_tile(uint8_t* dsm, int bx, int by, int z, int t) {
    uint16_t* As = (uint16_t*)dsm;
    uint16_t* Bs = As + NSTAGE * A_ST;

    int n0 = bx * BN;
    int m0 = by * BM;
    int wid = t >> 5, lane = t & 31;
    int wm = wid & 1, wn = (wid >> 1) & 1, kh = wid >> 2;

    const __nv_bfloat16* gA = g_lat + (size_t)m0 * IN_F + z * KSLICE;
    const __nv_bfloat16* gB = g_wT + (size_t)n0 * IN_F + z * KSLICE;

    float acc[2][4][4] = {};

    int rAq = wm * 32 + (lane & 15);
    int kA  = lane >> 4;
    int rBq = wn * 32 + ((lane >> 4) << 3) + (lane & 7);
    int kB  = (lane >> 3) & 1;

    load_tile(As, Bs, gA, gB, 0, t); CP_COMMIT;
    load_tile(As + A_ST, Bs + B_ST, gA, gB, BKK, t); CP_COMMIT;
    load_tile(As + 2 * A_ST, Bs + 2 * B_ST, gA, gB, 2 * BKK, t); CP_COMMIT;

    int buf = 0;
    for (int kc = 0; kc < NKC; kc++) {
        if (kc < NKC - 2)       { CP_WAIT2; }
        else if (kc == NKC - 2) { CP_WAIT1; }
        else                    { CP_WAIT0; }
        __syncthreads();

        if (kc + 3 < NKC) {
            int b3 = buf + 3; if (b3 >= NSTAGE) b3 -= NSTAGE;
            load_tile(As + b3 * A_ST, Bs + b3 * B_ST, gA, gB, (kc + 3) * BKK, t);
            CP_COMMIT;
        }

        const uint16_t* Ab = As + buf * A_ST;
        const uint16_t* Bb = Bs + buf * B_ST;
#pragma unroll
        for (int s = 0; s < 2; s++) {
            int cb = kh * 4 + s * 2;
            uint32_t af[2][4], bf[2][4];
#pragma unroll
            for (int mt = 0; mt < 2; mt++) {
                int r = rAq + mt * 16;
                int c = cb + kA;
                LDSM4(af[mt][0], af[mt][1], af[mt][2], af[mt][3],
                      cvta_s(&Ab[r * BKK + ((c ^ (r & 7)) << 3)]));
            }
#pragma unroll
            for (int j = 0; j < 2; j++) {
                int r = rBq + j * 16;
                int c = cb + kB;
                LDSM4(bf[j][0], bf[j][1], bf[j][2], bf[j][3],
                      cvta_s(&Bb[r * BKK + ((c ^ (r & 7)) << 3)]));
            }
#pragma unroll
            for (int mt = 0; mt < 2; mt++)
#pragma unroll
                for (int j = 0; j < 2; j++) {
                    MMA(acc[mt][2 * j],     af[mt], bf[j][0], bf[j][1]);
                    MMA(acc[mt][2 * j + 1], af[mt], bf[j][2], bf[j][3]);
                }
        }
        buf++; if (buf >= NSTAGE) buf = 0;
    }

    // merge k-halves
    __syncthreads();
    float* M = reinterpret_cast<float*>(dsm);
    float* afl = &acc[0][0][0];
    int quad = wm * 2 + wn;
    if (kh == 1) {
#pragma unroll
        for (int r = 0; r < 32; r++)
            M[quad * 1024 + r * 32 + lane] = afl[r];
    }
    __syncthreads();

    if (kh == 0) {
#pragma unroll
        for (int r = 0; r < 32; r++)
            afl[r] += M[quad * 1024 + r * 32 + lane];

        float* P = g_pred[z];
        int gid = lane >> 2, tig = lane & 3;
#pragma unroll
        for (int mt = 0; mt < 2; mt++)
#pragma unroll
            for (int nt = 0; nt < 4; nt++) {
                int r  = m0 + wm * 32 + mt * 16 + gid;
                int nc = n0 + wn * 32 + nt * 8 + tig * 2;
                *reinterpret_cast<float2*>(&P[(size_t)r * OUT_F + nc]) =
                    make_float2(acc[mt][nt][0], acc[mt][nt][1]);
                *reinterpret_cast<float2*>(&P[(size_t)(r + 8) * OUT_F + nc]) =
                    make_float2(acc[mt][nt][2], acc[mt][nt][3]);
            }
    }
}

// ---------------- k_mid: gemm z=0 tiles (bx<192) + weights k>=2048 ----------------
__global__ void __launch_bounds__(256, 3)
k_mid(const float* __restrict__ w) {
    extern __shared__ __align__(16) uint8_t dsm[];
    int bx = blockIdx.x;
    int t = threadIdx.x;
    if (bx < NTILE) {
        gemm_tile(dsm, bx % GX, bx / GX, 0, t);
    } else {
        int wbx = bx - NTILE;
        weight_block(w, 2048 + (wbx & 63) * 32, (wbx >> 6) * 32, NWB_HALF + wbx, t);
    }
}

// ---------------- k_gemmz: gemm z=1 ----------------
__global__ void __launch_bounds__(256, 3)
k_gemmz() {
    extern __shared__ __align__(16) uint8_t dsm[];
    gemm_tile(dsm, blockIdx.x, blockIdx.y, 1, threadIdx.x);
}

// ---------------- loss (R14 verbatim) ----------------
__global__ void k_loss(const float* __restrict__ ts,
                       float* __restrict__ out, int out_size) {
    __shared__ float s_red[8], s_red2[8];
    __shared__ int s_last;
    int t = threadIdx.x, bid = blockIdx.x;
    int base = (bid * 256 + t) * 4;
    int r = base / OUT_F, n = base % OUT_F;

    float4 p0 = *reinterpret_cast<const float4*>(&g_pred[0][base]);
    float4 p1 = *reinterpret_cast<const float4*>(&g_pred[1][base]);
    float e0 = fmaf(p0.x + p1.x, 1.f / 255.f, -tval(ts, r, n));
    float e1 = fmaf(p0.y + p1.y, 1.f / 255.f, -tval(ts, r, n + 1));
    float e2 = fmaf(p0.z + p1.z, 1.f / 255.f, -tval(ts, r, n + 2));
    float e3 = fmaf(p0.w + p1.w, 1.f / 255.f, -tval(ts, r, n + 3));
    float lsum = e0 * e0 + e1 * e1 + e2 * e2 + e3 * e3;

#pragma unroll
    for (int o = 16; o > 0; o >>= 1)
        lsum += __shfl_xor_sync(0xffffffffu, lsum, o);
    if ((t & 31) == 0) s_red[t >> 5] = lsum;
    __syncthreads();

    if (t == 0) {
        float s = 0.f;
#pragma unroll
        for (int i = 0; i < 8; i++) s += s_red[i];
        g_recon_part[bid] = s;
        __threadfence();
        int old = atomicAdd(&g_ticket, 1);
        s_last = (old == NLOSS - 1) ? 1 : 0;
    }
    __syncthreads();

    if (s_last) {
        float rr = 0.f, ss = 0.f;
        for (int i = t; i < 3072; i += 256) rr += __ldcg(&g_reg_part[i]);
        for (int i = t; i < NLOSS; i += 256) ss += __ldcg(&g_recon_part[i]);
#pragma unroll
        for (int o = 16; o > 0; o >>= 1) {
            rr += __shfl_xor_sync(0xffffffffu, rr, o);
            ss += __shfl_xor_sync(0xffffffffu, ss, o);
        }
        if ((t & 31) == 0) { s_red[t >> 5] = rr; s_red2[t >> 5] = ss; }
        __syncthreads();
        if (t == 0) {
            float R = 0.f, S = 0.f;
#pragma unroll
            for (int i = 0; i < 8; i++) { R += s_red[i]; S += s_red2[i]; }
            float recon = S * (1.0f / ((float)BATCH * OUT_F));
            float reg   = 0.001f * R * (1.0f / ((float)IN_F * (float)BITS));
            if (out_size > 0) out[0] = recon + reg;
            if (out_size > 1) out[1] = recon;
            if (out_size > 2) out[2] = reg;
            g_ticket = 0;
        }
    }
}

// ---------------- launch ----------------
extern "C" void kernel_launch(void* const* d_in, const int* in_sizes, int n_in,
                              void* d_out, int out_size) {
    const float* latent   = (const float*)d_in[0];
    const float* true_sum = (const float*)d_in[1];
    const float* weight   = (const float*)d_in[2];

    static int smem_set = 0;
    if (!smem_set) {
        cudaFuncSetAttribute(k_mid, cudaFuncAttributeMaxDynamicSharedMemorySize,
                             DSMEM_BYTES);
        cudaFuncSetAttribute(k_gemmz, cudaFuncAttributeMaxDynamicSharedMemorySize,
                             DSMEM_BYTES);
        smem_set = 1;
    }

    k_preA<<<NWB_HALF + 1024, 256>>>(weight, latent);
    k_mid<<<NTILE + NWB_HALF, 256, DSMEM_BYTES>>>(weight);
    k_gemmz<<<dim3(GX, GY), 256, DSMEM_BYTES>>>();
    k_loss<<<NLOSS, 256>>>(true_sum, (float*)d_out, out_size);
}

// round 16
// speedup vs baseline: 1.0562x; 1.0562x over previous
#include <cuda_runtime.h>
#include <cuda_bf16.h>
#include <cstdint>

#define IN_F   4096
#define OUT_F  768
#define BITS   6144
#define BATCH  1024

#define BM 64
#define BN 64
#define BKK 64
#define KSPLIT 2
#define KSLICE (IN_F / KSPLIT)   // 2048
#define NKC (KSLICE / BKK)       // 32
#define NSTAGE 4
#define GX (OUT_F / BN)          // 12
#define GY (BATCH / BM)          // 16
#define A_ST (BM * BKK)
#define B_ST (BN * BKK)
#define DSMEM_BYTES (NSTAGE * (A_ST + B_ST) * 2)   // 65536
#define NLOSS 768
#define NW_BLK 3072              // weight blocks
#define NL_BLK 1024              // latent blocks
#define NT_BLK 384               // int_sum blocks

// ---------------- device scratch ----------------
__device__ __nv_bfloat16 g_wT[(size_t)OUT_F * IN_F];
__device__ __nv_bfloat16 g_lat[(size_t)BATCH * IN_F];
__device__ float g_t[(size_t)BATCH * OUT_F];            // int_sum/255
__device__ float g_pred[KSPLIT][(size_t)BATCH * OUT_F];
__device__ float g_reg_part[NW_BLK];
__device__ float g_recon_part[NLOSS];
__device__ int   g_ticket;

// ---------------- helpers ----------------
__device__ __forceinline__ float tanh_fast(float x) {
    float y; asm("tanh.approx.f32 %0, %1;" : "=f"(y) : "f"(x)); return y;
}
__device__ __forceinline__ uint32_t cvta_s(const void* p) {
    return (uint32_t)__cvta_generic_to_shared(p);
}
#define CP_ASYNC16(s, g) asm volatile("cp.async.cg.shared.global [%0], [%1], 16;\n" :: "r"(s), "l"(g))
#define CP_COMMIT        asm volatile("cp.async.commit_group;\n" ::: "memory")
#define CP_WAIT0         asm volatile("cp.async.wait_group 0;\n" ::: "memory")
#define CP_WAIT1         asm volatile("cp.async.wait_group 1;\n" ::: "memory")
#define CP_WAIT2         asm volatile("cp.async.wait_group 2;\n" ::: "memory")
#define LDSM4(r0, r1, r2, r3, a) \
    asm volatile("ldmatrix.sync.aligned.m8n8.x4.shared.b16 {%0,%1,%2,%3}, [%4];\n" \
                 : "=r"(r0), "=r"(r1), "=r"(r2), "=r"(r3) : "r"(a))
#define MMA(d, a, b0, b1) \
    asm volatile("mma.sync.aligned.m16n8k16.row.col.f32.bf16.bf16.f32 " \
                 "{%0,%1,%2,%3},{%4,%5,%6,%7},{%8,%9},{%0,%1,%2,%3};\n" \
                 : "+f"(d[0]), "+f"(d[1]), "+f"(d[2]), "+f"(d[3]) \
                 : "r"(a[0]), "r"(a[1]), "r"(a[2]), "r"(a[3]), "r"(b0), "r"(b1))

// ---------------- fused pre-pass: weights + latent + int_sum ----------------
__global__ void k_pre(const float* __restrict__ w, const float* __restrict__ lat,
                      const float* __restrict__ ts) {
    int bx = blockIdx.x;
    int t = threadIdx.x;

    if (bx < NW_BLK) {
        __shared__ float s_iw[32][33];
        __shared__ float s_red[8];
        const float pwh[8] = {0.5f, 1.f, 2.f, 4.f, 8.f, 16.f, 32.f, -64.f};

        int k0 = (bx & 127) * 32;
        int n0 = (bx >> 7) * 32;

        float regloc = 0.f;
#pragma unroll
        for (int i = 0; i < 4; i++) {
            int c = t + i * 256;
            int kk = c >> 5, nn = c & 31;
            const float4* p = reinterpret_cast<const float4*>(
                w + (size_t)(k0 + kk) * BITS + (size_t)(n0 + nn) * 8);
            float4 w0 = p[0], w1 = p[1];
            float xs[8] = {w0.x, w0.y, w0.z, w0.w, w1.x, w1.y, w1.z, w1.w};
            float iwt = 0.f, sab = 0.f;
#pragma unroll
            for (int b = 0; b < 8; b++) {
                float th = tanh_fast(0.5f * xs[b]);
                iwt = fmaf(th, pwh[b], iwt);
                sab += fabsf(th);
            }
            s_iw[kk][nn] = iwt - 0.5f;
            regloc += fmaf(-0.5f, sab, 4.0f);
        }
        __syncthreads();
#pragma unroll
        for (int i = 0; i < 4; i++) {
            int c = t + i * 256;
            int nn = c >> 5, kk = c & 31;
            g_wT[(size_t)(n0 + nn) * IN_F + (k0 + kk)] = __float2bfloat16(s_iw[kk][nn]);
        }
#pragma unroll
        for (int o = 16; o > 0; o >>= 1)
            regloc += __shfl_xor_sync(0xffffffffu, regloc, o);
        if ((t & 31) == 0) s_red[t >> 5] = regloc;
        __syncthreads();
        if (t == 0) {
            float s = 0.f;
#pragma unroll
            for (int i = 0; i < 8; i++) s += s_red[i];
            g_reg_part[bx] = s;
        }
    } else if (bx < NW_BLK + NL_BLK) {
        int i = (bx - NW_BLK) * 256 + t;
        const int stride = NL_BLK * 256;
        const float4* src = reinterpret_cast<const float4*>(lat);
        __nv_bfloat162* o = reinterpret_cast<__nv_bfloat162*>(g_lat);
        float4 v[4];
#pragma unroll
        for (int j = 0; j < 4; j++) v[j] = src[i + j * stride];
#pragma unroll
        for (int j = 0; j < 4; j++) {
            int idx = i + j * stride;
            o[2 * idx]     = __floats2bfloat162_rn(v[j].x, v[j].y);
            o[2 * idx + 1] = __floats2bfloat162_rn(v[j].z, v[j].w);
        }
    } else {
        // int_sum/255: 8 outputs per thread, coalesced
        int c0 = ((bx - NW_BLK - NL_BLK) * 256 + t) * 8;
        const float4* p = reinterpret_cast<const float4*>(ts + (size_t)c0 * 8);
        float ot[8];
#pragma unroll
        for (int j = 0; j < 8; j++) {
            float4 a = p[2 * j], b = p[2 * j + 1];
            ot[j] = (a.x + 2.f * a.y + 4.f * a.z + 8.f * a.w
                     + 16.f * b.x + 32.f * b.y + 64.f * b.z - 128.f * b.w)
                    * (1.0f / 255.0f);
        }
        float4* q = reinterpret_cast<float4*>(&g_t[c0]);
        q[0] = make_float4(ot[0], ot[1], ot[2], ot[3]);
        q[1] = make_float4(ot[4], ot[5], ot[6], ot[7]);
    }
}

// stage loader (R14 verbatim)
__device__ __forceinline__ void load_tile(
    uint16_t* Asb, uint16_t* Bsb,
    const __nv_bfloat16* gA, const __nv_bfloat16* gB, int kbase, int t)
{
#pragma unroll
    for (int j = 0; j < 2; j++) {
        int id = t + j * 256;
        int row = id >> 3, c = id & 7;
        int sw = (c ^ (row & 7)) << 3;
        CP_ASYNC16(cvta_s(&Asb[row * BKK + sw]),
                   gA + (size_t)row * IN_F + kbase + c * 8);
        CP_ASYNC16(cvta_s(&Bsb[row * BKK + sw]),
                   gB + (size_t)row * IN_F + kbase + c * 8);
    }
}

// split-K GEMM (R14 verbatim): in-CTA k-split, warp tile 32x32, 4-stage cp.async
__global__ void __launch_bounds__(256, 3)
k_gemm() {
    extern __shared__ __align__(16) uint8_t dsm[];
    uint16_t* As = (uint16_t*)dsm;
    uint16_t* Bs = As + NSTAGE * A_ST;

    int n0 = blockIdx.x * BN;
    int m0 = blockIdx.y * BM;
    int z  = blockIdx.z;
    int t = threadIdx.x;
    int wid = t >> 5, lane = t & 31;
    int wm = wid & 1, wn = (wid >> 1) & 1, kh = wid >> 2;

    const __nv_bfloat16* gA = g_lat + (size_t)m0 * IN_F + z * KSLICE;
    const __nv_bfloat16* gB = g_wT + (size_t)n0 * IN_F + z * KSLICE;

    float acc[2][4][4] = {};

    int rAq = wm * 32 + (lane & 15);
    int kA  = lane >> 4;
    int rBq = wn * 32 + ((lane >> 4) << 3) + (lane & 7);
    int kB  = (lane >> 3) & 1;

    load_tile(As, Bs, gA, gB, 0, t); CP_COMMIT;
    load_tile(As + A_ST, Bs + B_ST, gA, gB, BKK, t); CP_COMMIT;
    load_tile(As + 2 * A_ST, Bs + 2 * B_ST, gA, gB, 2 * BKK, t); CP_COMMIT;

    int buf = 0;
    for (int kc = 0; kc < NKC; kc++) {
        if (kc < NKC - 2)       { CP_WAIT2; }
        else if (kc == NKC - 2) { CP_WAIT1; }
        else                    { CP_WAIT0; }
        __syncthreads();

        if (kc + 3 < NKC) {
            int b3 = buf + 3; if (b3 >= NSTAGE) b3 -= NSTAGE;
            load_tile(As + b3 * A_ST, Bs + b3 * B_ST, gA, gB, (kc + 3) * BKK, t);
            CP_COMMIT;
        }

        const uint16_t* Ab = As + buf * A_ST;
        const uint16_t* Bb = Bs + buf * B_ST;
#pragma unroll
        for (int s = 0; s < 2; s++) {
            int cb = kh * 4 + s * 2;
            uint32_t af[2][4], bf[2][4];
#pragma unroll
            for (int mt = 0; mt < 2; mt++) {
                int r = rAq + mt * 16;
                int c = cb + kA;
                LDSM4(af[mt][0], af[mt][1], af[mt][2], af[mt][3],
                      cvta_s(&Ab[r * BKK + ((c ^ (r & 7)) << 3)]));
            }
#pragma unroll
            for (int j = 0; j < 2; j++) {
                int r = rBq + j * 16;
                int c = cb + kB;
                LDSM4(bf[j][0], bf[j][1], bf[j][2], bf[j][3],
                      cvta_s(&Bb[r * BKK + ((c ^ (r & 7)) << 3)]));
            }
#pragma unroll
            for (int mt = 0; mt < 2; mt++)
#pragma unroll
                for (int j = 0; j < 2; j++) {
                    MMA(acc[mt][2 * j],     af[mt], bf[j][0], bf[j][1]);
                    MMA(acc[mt][2 * j + 1], af[mt], bf[j][2], bf[j][3]);
                }
        }
        buf++; if (buf >= NSTAGE) buf = 0;
    }

    // merge k-halves
    __syncthreads();
    float* M = reinterpret_cast<float*>(dsm);
    float* afl = &acc[0][0][0];
    int quad = wm * 2 + wn;
    if (kh == 1) {
#pragma unroll
        for (int r = 0; r < 32; r++)
            M[quad * 1024 + r * 32 + lane] = afl[r];
    }
    __syncthreads();

    if (kh == 0) {
#pragma unroll
        for (int r = 0; r < 32; r++)
            afl[r] += M[quad * 1024 + r * 32 + lane];

        float* P = g_pred[z];
        int gid = lane >> 2, tig = lane & 3;
#pragma unroll
        for (int mt = 0; mt < 2; mt++)
#pragma unroll
            for (int nt = 0; nt < 4; nt++) {
                int r  = m0 + wm * 32 + mt * 16 + gid;
                int nc = n0 + wn * 32 + nt * 8 + tig * 2;
                *reinterpret_cast<float2*>(&P[(size_t)r * OUT_F + nc]) =
                    make_float2(acc[mt][nt][0], acc[mt][nt][1]);
                *reinterpret_cast<float2*>(&P[(size_t)(r + 8) * OUT_F + nc]) =
                    make_float2(acc[mt][nt][2], acc[mt][nt][3]);
            }
    }
}

// loss: pred = p0+p1 vs precomputed g_t — 9MB total traffic
__global__ void k_loss(float* __restrict__ out, int out_size) {
    __shared__ float s_red[8], s_red2[8];
    __shared__ int s_last;
    int t = threadIdx.x, bid = blockIdx.x;
    int base = (bid * 256 + t) * 4;

    float4 p0 = *reinterpret_cast<const float4*>(&g_pred[0][base]);
    float4 p1 = *reinterpret_cast<const float4*>(&g_pred[1][base]);
    float4 tv = *reinterpret_cast<const float4*>(&g_t[base]);
    float e0 = fmaf(p0.x + p1.x, 1.f / 255.f, -tv.x);
    float e1 = fmaf(p0.y + p1.y, 1.f / 255.f, -tv.y);
    float e2 = fmaf(p0.z + p1.z, 1.f / 255.f, -tv.z);
    float e3 = fmaf(p0.w + p1.w, 1.f / 255.f, -tv.w);
    float lsum = e0 * e0 + e1 * e1 + e2 * e2 + e3 * e3;

#pragma unroll
    for (int o = 16; o > 0; o >>= 1)
        lsum += __shfl_xor_sync(0xffffffffu, lsum, o);
    if ((t & 31) == 0) s_red[t >> 5] = lsum;
    __syncthreads();

    if (t == 0) {
        float s = 0.f;
#pragma unroll
        for (int i = 0; i < 8; i++) s += s_red[i];
        g_recon_part[bid] = s;
        __threadfence();
        int old = atomicAdd(&g_ticket, 1);
        s_last = (old == NLOSS - 1) ? 1 : 0;
    }
    __syncthreads();

    if (s_last) {
        float rr = 0.f, ss = 0.f;
        for (int i = t; i < NW_BLK; i += 256) rr += __ldcg(&g_reg_part[i]);
        for (int i = t; i < NLOSS; i += 256) ss += __ldcg(&g_recon_part[i]);
#pragma unroll
        for (int o = 16; o > 0; o >>= 1) {
            rr += __shfl_xor_sync(0xffffffffu, rr, o);
            ss += __shfl_xor_sync(0xffffffffu, ss, o);
        }
        if ((t & 31) == 0) { s_red[t >> 5] = rr; s_red2[t >> 5] = ss; }
        __syncthreads();
        if (t == 0) {
            float R = 0.f, S = 0.f;
#pragma unroll
            for (int i = 0; i < 8; i++) { R += s_red[i]; S += s_red2[i]; }
            float recon = S * (1.0f / ((float)BATCH * OUT_F));
            float reg   = 0.001f * R * (1.0f / ((float)IN_F * (float)BITS));
            if (out_size > 0) out[0] = recon + reg;
            if (out_size > 1) out[1] = recon;
            if (out_size > 2) out[2] = reg;
            g_ticket = 0;
        }
    }
}

// ---------------- launch ----------------
extern "C" void kernel_launch(void* const* d_in, const int* in_sizes, int n_in,
                              void* d_out, int out_size) {
    const float* latent   = (const float*)d_in[0];
    const float* true_sum = (const float*)d_in[1];
    const float* weight   = (const float*)d_in[2];

    static int smem_set = 0;
    if (!smem_set) {
        cudaFuncSetAttribute(k_gemm, cudaFuncAttributeMaxDynamicSharedMemorySize,
                             DSMEM_BYTES);
        smem_set = 1;
    }

    k_pre<<<NW_BLK + NL_BLK + NT_BLK, 256>>>(weight, latent, true_sum);
    k_gemm<<<dim3(GX, GY, KSPLIT), 256, DSMEM_BYTES>>>();
    k_loss<<<NLOSS, 256>>>((float*)d_out, out_size);
}

// round 17
// speedup vs baseline: 1.1654x; 1.1034x over previous
#include <cuda_runtime.h>
#include <cuda_bf16.h>
#include <cstdint>

#define IN_F   4096
#define OUT_F  768
#define BITS   6144
#define BATCH  1024

#define BM 64
#define BN 64
#define BKK 64
#define KSPLIT 2
#define KSLICE (IN_F / KSPLIT)   // 2048
#define NKC (KSLICE / BKK)       // 32
#define NSTAGE 4
#define GX (OUT_F / BN)          // 12
#define GY (BATCH / BM)          // 16
#define A_ST (BM * BKK)
#define B_ST (BN * BKK)
#define DSMEM_BYTES (NSTAGE * (A_ST + B_ST) * 2)   // 65536
#define NLOSS 768
#define NT_BLK 384               // int_sum blocks  [0, 384)
#define NL_BLK 1024              // latent blocks   [384, 1408)
#define NW_BLK 3072              // weight blocks   [1408, 4480)

// ---------------- device scratch ----------------
__device__ __nv_bfloat16 g_wT[(size_t)OUT_F * IN_F];
__device__ __nv_bfloat16 g_lat[(size_t)BATCH * IN_F];
__device__ float g_t[(size_t)BATCH * OUT_F];            // int_sum/255
__device__ float g_pred[KSPLIT][(size_t)BATCH * OUT_F];
__device__ float g_reg_part[NW_BLK];
__device__ float g_recon_part[NLOSS];
__device__ int   g_ticket;

// ---------------- helpers ----------------
__device__ __forceinline__ float tanh_fast(float x) {
    float y; asm("tanh.approx.f32 %0, %1;" : "=f"(y) : "f"(x)); return y;
}
__device__ __forceinline__ uint32_t cvta_s(const void* p) {
    return (uint32_t)__cvta_generic_to_shared(p);
}
#define CP_ASYNC16(s, g) asm volatile("cp.async.cg.shared.global [%0], [%1], 16;\n" :: "r"(s), "l"(g))
#define CP_COMMIT        asm volatile("cp.async.commit_group;\n" ::: "memory")
#define CP_WAIT0         asm volatile("cp.async.wait_group 0;\n" ::: "memory")
#define CP_WAIT1         asm volatile("cp.async.wait_group 1;\n" ::: "memory")
#define CP_WAIT2         asm volatile("cp.async.wait_group 2;\n" ::: "memory")
#define LDSM4(r0, r1, r2, r3, a) \
    asm volatile("ldmatrix.sync.aligned.m8n8.x4.shared.b16 {%0,%1,%2,%3}, [%4];\n" \
                 : "=r"(r0), "=r"(r1), "=r"(r2), "=r"(r3) : "r"(a))
#define MMA(d, a, b0, b1) \
    asm volatile("mma.sync.aligned.m16n8k16.row.col.f32.bf16.bf16.f32 " \
                 "{%0,%1,%2,%3},{%4,%5,%6,%7},{%8,%9},{%0,%1,%2,%3};\n" \
                 : "+f"(d[0]), "+f"(d[1]), "+f"(d[2]), "+f"(d[3]) \
                 : "r"(a[0]), "r"(a[1]), "r"(a[2]), "r"(a[3]), "r"(b0), "r"(b1))

// ---------------- fused pre-pass: int_sum + latent + weights (ordered) ----------------
__global__ void k_pre(const float* __restrict__ w, const float* __restrict__ lat,
                      const float* __restrict__ ts) {
    int bx = blockIdx.x;
    int t = threadIdx.x;

    if (bx < NT_BLK) {
        // int_sum/255: 8 outputs per thread, contiguous 128B read per thread
        int c0 = (bx * 256 + t) * 8;
        const float4* p = reinterpret_cast<const float4*>(ts + (size_t)c0 * 8);
        float ot[8];
#pragma unroll
        for (int j = 0; j < 8; j++) {
            float4 a = p[2 * j], b = p[2 * j + 1];
            ot[j] = (a.x + 2.f * a.y + 4.f * a.z + 8.f * a.w
                     + 16.f * b.x + 32.f * b.y + 64.f * b.z - 128.f * b.w)
                    * (1.0f / 255.0f);
        }
        float4* q = reinterpret_cast<float4*>(&g_t[c0]);
        q[0] = make_float4(ot[0], ot[1], ot[2], ot[3]);
        q[1] = make_float4(ot[4], ot[5], ot[6], ot[7]);
    } else if (bx < NT_BLK + NL_BLK) {
        int i = (bx - NT_BLK) * 256 + t;
        const int stride = NL_BLK * 256;
        const float4* src = reinterpret_cast<const float4*>(lat);
        __nv_bfloat162* o = reinterpret_cast<__nv_bfloat162*>(g_lat);
        float4 v[4];
#pragma unroll
        for (int j = 0; j < 4; j++) v[j] = src[i + j * stride];
#pragma unroll
        for (int j = 0; j < 4; j++) {
            int idx = i + j * stride;
            o[2 * idx]     = __floats2bfloat162_rn(v[j].x, v[j].y);
            o[2 * idx + 1] = __floats2bfloat162_rn(v[j].z, v[j].w);
        }
    } else {
        int wb = bx - NT_BLK - NL_BLK;
        __shared__ float s_iw[32][33];
        __shared__ float s_red[8];
        const float pwh[8] = {0.5f, 1.f, 2.f, 4.f, 8.f, 16.f, 32.f, -64.f};

        int k0 = (wb & 127) * 32;
        int n0 = (wb >> 7) * 32;

        float regloc = 0.f;
#pragma unroll
        for (int i = 0; i < 4; i++) {
            int c = t + i * 256;
            int kk = c >> 5, nn = c & 31;
            const float4* p = reinterpret_cast<const float4*>(
                w + (size_t)(k0 + kk) * BITS + (size_t)(n0 + nn) * 8);
            float4 w0 = p[0], w1 = p[1];
            float xs[8] = {w0.x, w0.y, w0.z, w0.w, w1.x, w1.y, w1.z, w1.w};
            float iwt = 0.f, sab = 0.f;
#pragma unroll
            for (int b = 0; b < 8; b++) {
                float th = tanh_fast(0.5f * xs[b]);
                iwt = fmaf(th, pwh[b], iwt);
                sab += fabsf(th);
            }
            s_iw[kk][nn] = iwt - 0.5f;
            regloc += fmaf(-0.5f, sab, 4.0f);
        }
        __syncthreads();
#pragma unroll
        for (int i = 0; i < 4; i++) {
            int c = t + i * 256;
            int nn = c >> 5, kk = c & 31;
            g_wT[(size_t)(n0 + nn) * IN_F + (k0 + kk)] = __float2bfloat16(s_iw[kk][nn]);
        }
#pragma unroll
        for (int o = 16; o > 0; o >>= 1)
            regloc += __shfl_xor_sync(0xffffffffu, regloc, o);
        if ((t & 31) == 0) s_red[t >> 5] = regloc;
        __syncthreads();
        if (t == 0) {
            float s = 0.f;
#pragma unroll
            for (int i = 0; i < 8; i++) s += s_red[i];
            g_reg_part[wb] = s;
        }
    }
}

// stage loader (R14 verbatim)
__device__ __forceinline__ void load_tile(
    uint16_t* Asb, uint16_t* Bsb,
    const __nv_bfloat16* gA, const __nv_bfloat16* gB, int kbase, int t)
{
#pragma unroll
    for (int j = 0; j < 2; j++) {
        int id = t + j * 256;
        int row = id >> 3, c = id & 7;
        int sw = (c ^ (row & 7)) << 3;
        CP_ASYNC16(cvta_s(&Asb[row * BKK + sw]),
                   gA + (size_t)row * IN_F + kbase + c * 8);
        CP_ASYNC16(cvta_s(&Bsb[row * BKK + sw]),
                   gB + (size_t)row * IN_F + kbase + c * 8);
    }
}

// split-K GEMM (R14 verbatim): in-CTA k-split, warp tile 32x32, 4-stage cp.async
__global__ void __launch_bounds__(256, 3)
k_gemm() {
    extern __shared__ __align__(16) uint8_t dsm[];
    uint16_t* As = (uint16_t*)dsm;
    uint16_t* Bs = As + NSTAGE * A_ST;

    int n0 = blockIdx.x * BN;
    int m0 = blockIdx.y * BM;
    int z  = blockIdx.z;
    int t = threadIdx.x;
    int wid = t >> 5, lane = t & 31;
    int wm = wid & 1, wn = (wid >> 1) & 1, kh = wid >> 2;

    const __nv_bfloat16* gA = g_lat + (size_t)m0 * IN_F + z * KSLICE;
    const __nv_bfloat16* gB = g_wT + (size_t)n0 * IN_F + z * KSLICE;

    float acc[2][4][4] = {};

    int rAq = wm * 32 + (lane & 15);
    int kA  = lane >> 4;
    int rBq = wn * 32 + ((lane >> 4) << 3) + (lane & 7);
    int kB  = (lane >> 3) & 1;

    load_tile(As, Bs, gA, gB, 0, t); CP_COMMIT;
    load_tile(As + A_ST, Bs + B_ST, gA, gB, BKK, t); CP_COMMIT;
    load_tile(As + 2 * A_ST, Bs + 2 * B_ST, gA, gB, 2 * BKK, t); CP_COMMIT;

    int buf = 0;
    for (int kc = 0; kc < NKC; kc++) {
        if (kc < NKC - 2)       { CP_WAIT2; }
        else if (kc == NKC - 2) { CP_WAIT1; }
        else                    { CP_WAIT0; }
        __syncthreads();

        if (kc + 3 < NKC) {
            int b3 = buf + 3; if (b3 >= NSTAGE) b3 -= NSTAGE;
            load_tile(As + b3 * A_ST, Bs + b3 * B_ST, gA, gB, (kc + 3) * BKK, t);
            CP_COMMIT;
        }

        const uint16_t* Ab = As + buf * A_ST;
        const uint16_t* Bb = Bs + buf * B_ST;
#pragma unroll
        for (int s = 0; s < 2; s++) {
            int cb = kh * 4 + s * 2;
            uint32_t af[2][4], bf[2][4];
#pragma unroll
            for (int mt = 0; mt < 2; mt++) {
                int r = rAq + mt * 16;
                int c = cb + kA;
                LDSM4(af[mt][0], af[mt][1], af[mt][2], af[mt][3],
                      cvta_s(&Ab[r * BKK + ((c ^ (r & 7)) << 3)]));
            }
#pragma unroll
            for (int j = 0; j < 2; j++) {
                int r = rBq + j * 16;
                int c = cb + kB;
                LDSM4(bf[j][0], bf[j][1], bf[j][2], bf[j][3],
                      cvta_s(&Bb[r * BKK + ((c ^ (r & 7)) << 3)]));
            }
#pragma unroll
            for (int mt = 0; mt < 2; mt++)
#pragma unroll
                for (int j = 0; j < 2; j++) {
                    MMA(acc[mt][2 * j],     af[mt], bf[j][0], bf[j][1]);
                    MMA(acc[mt][2 * j + 1], af[mt], bf[j][2], bf[j][3]);
                }
        }
        buf++; if (buf >= NSTAGE) buf = 0;
    }

    // merge k-halves
    __syncthreads();
    float* M = reinterpret_cast<float*>(dsm);
    float* afl = &acc[0][0][0];
    int quad = wm * 2 + wn;
    if (kh == 1) {
#pragma unroll
        for (int r = 0; r < 32; r++)
            M[quad * 1024 + r * 32 + lane] = afl[r];
    }
    __syncthreads();

    if (kh == 0) {
#pragma unroll
        for (int r = 0; r < 32; r++)
            afl[r] += M[quad * 1024 + r * 32 + lane];

        float* P = g_pred[z];
        int gid = lane >> 2, tig = lane & 3;
#pragma unroll
        for (int mt = 0; mt < 2; mt++)
#pragma unroll
            for (int nt = 0; nt < 4; nt++) {
                int r  = m0 + wm * 32 + mt * 16 + gid;
                int nc = n0 + wn * 32 + nt * 8 + tig * 2;
                *reinterpret_cast<float2*>(&P[(size_t)r * OUT_F + nc]) =
                    make_float2(acc[mt][nt][0], acc[mt][nt][1]);
                *reinterpret_cast<float2*>(&P[(size_t)(r + 8) * OUT_F + nc]) =
                    make_float2(acc[mt][nt][2], acc[mt][nt][3]);
            }
    }
}

// loss: pred = p0+p1 vs precomputed g_t — 9MB linear traffic
__global__ void k_loss(float* __restrict__ out, int out_size) {
    __shared__ float s_red[8], s_red2[8];
    __shared__ int s_last;
    int t = threadIdx.x, bid = blockIdx.x;
    int base = (bid * 256 + t) * 4;

    float4 p0 = *reinterpret_cast<const float4*>(&g_pred[0][base]);
    float4 p1 = *reinterpret_cast<const float4*>(&g_pred[1][base]);
    float4 tv = *reinterpret_cast<const float4*>(&g_t[base]);
    float e0 = fmaf(p0.x + p1.x, 1.f / 255.f, -tv.x);
    float e1 = fmaf(p0.y + p1.y, 1.f / 255.f, -tv.y);
    float e2 = fmaf(p0.z + p1.z, 1.f / 255.f, -tv.z);
    float e3 = fmaf(p0.w + p1.w, 1.f / 255.f, -tv.w);
    float lsum = e0 * e0 + e1 * e1 + e2 * e2 + e3 * e3;

#pragma unroll
    for (int o = 16; o > 0; o >>= 1)
        lsum += __shfl_xor_sync(0xffffffffu, lsum, o);
    if ((t & 31) == 0) s_red[t >> 5] = lsum;
    __syncthreads();

    if (t == 0) {
        float s = 0.f;
#pragma unroll
        for (int i = 0; i < 8; i++) s += s_red[i];
        g_recon_part[bid] = s;
        __threadfence();
        int old = atomicAdd(&g_ticket, 1);
        s_last = (old == NLOSS - 1) ? 1 : 0;
    }
    __syncthreads();

    if (s_last) {
        float rr = 0.f, ss = 0.f;
        for (int i = t; i < NW_BLK; i += 256) rr += __ldcg(&g_reg_part[i]);
        for (int i = t; i < NLOSS; i += 256) ss += __ldcg(&g_recon_part[i]);
#pragma unroll
        for (int o = 16; o > 0; o >>= 1) {
            rr += __shfl_xor_sync(0xffffffffu, rr, o);
            ss += __shfl_xor_sync(0xffffffffu, ss, o);
        }
        if ((t & 31) == 0) { s_red[t >> 5] = rr; s_red2[t >> 5] = ss; }
        __syncthreads();
        if (t == 0) {
            float R = 0.f, S = 0.f;
#pragma unroll
            for (int i = 0; i < 8; i++) { R += s_red[i]; S += s_red2[i]; }
            float recon = S * (1.0f / ((float)BATCH * OUT_F));
            float reg   = 0.001f * R * (1.0f / ((float)IN_F * (float)BITS));
            if (out_size > 0) out[0] = recon + reg;
            if (out_size > 1) out[1] = recon;
            if (out_size > 2) out[2] = reg;
            g_ticket = 0;
        }
    }
}

// ---------------- launch ----------------
extern "C" void kernel_launch(void* const* d_in, const int* in_sizes, int n_in,
                              void* d_out, int out_size) {
    const float* latent   = (const float*)d_in[0];
    const float* true_sum = (const float*)d_in[1];
    const float* weight   = (const float*)d_in[2];

    static int smem_set = 0;
    if (!smem_set) {
        cudaFuncSetAttribute(k_gemm, cudaFuncAttributeMaxDynamicSharedMemorySize,
                             DSMEM_BYTES);
        smem_set = 1;
    }

    k_pre<<<NT_BLK + NL_BLK + NW_BLK, 256>>>(weight, latent, true_sum);
    k_gemm<<<dim3(GX, GY, KSPLIT), 256, DSMEM_BYTES>>>();
    k_loss<<<NLOSS, 256>>>((float*)d_out, out_size);
}